// round 9
// baseline (speedup 1.0000x reference)
#include <cuda_runtime.h>
#include <cuda_fp16.h>
#include <cstdint>

// ---------------- problem constants -----------------------------------------
#define MROWS 8192      // B*C = 32*256
#define VIN   6890
#define VOUT  1723
#define KPAD  6912      // 108 * 64
#define NPAD  1792      // 14 * 128
#define NSPLIT 2
#define KSPLIT (KPAD / NSPLIT)   // 3456

// fp16 scratch (device globals; no runtime allocation)
__device__ __align__(16) __half g_Xh[(size_t)MROWS * KPAD];  // ~113 MB
__device__ __align__(16) __half g_Mh[(size_t)NPAD  * KPAD];  // ~25 MB

// ---------------- vectorized fp32 -> fp16 conversion ------------------------
__global__ void convert_x_v(const float* __restrict__ x) {
    int k8 = blockIdx.x * blockDim.x + threadIdx.x;
    if (k8 >= KPAD / 8) return;
    int row = blockIdx.y;
    int k = k8 * 8;
    const float* src = x + (size_t)row * VIN + k;
    __align__(16) __half h[8];
    if (k + 8 <= VIN) {
        #pragma unroll
        for (int j = 0; j < 4; ++j) {
            float2 f = *reinterpret_cast<const float2*>(src + 2 * j);
            h[2 * j]     = __float2half(f.x);
            h[2 * j + 1] = __float2half(f.y);
        }
    } else {
        #pragma unroll
        for (int j = 0; j < 8; ++j)
            h[j] = (k + j < VIN) ? __float2half(src[j]) : __float2half(0.0f);
    }
    *reinterpret_cast<uint4*>(&g_Xh[(size_t)row * KPAD + k]) =
        *reinterpret_cast<const uint4*>(h);
}

__global__ void convert_m_v(const float* __restrict__ m) {
    int k8 = blockIdx.x * blockDim.x + threadIdx.x;
    if (k8 >= KPAD / 8) return;
    int row = blockIdx.y;
    int k = k8 * 8;
    __align__(16) __half h[8];
    if (row < VOUT) {
        const float* src = m + (size_t)row * VIN + k;
        if (k + 8 <= VIN) {
            #pragma unroll
            for (int j = 0; j < 4; ++j) {
                float2 f = *reinterpret_cast<const float2*>(src + 2 * j);
                h[2 * j]     = __float2half(f.x);
                h[2 * j + 1] = __float2half(f.y);
            }
        } else {
            #pragma unroll
            for (int j = 0; j < 8; ++j)
                h[j] = (k + j < VIN) ? __float2half(src[j]) : __float2half(0.0f);
        }
    } else {
        #pragma unroll
        for (int j = 0; j < 8; ++j) h[j] = __float2half(0.0f);
    }
    *reinterpret_cast<uint4*>(&g_Mh[(size_t)row * KPAD + k]) =
        *reinterpret_cast<const uint4*>(h);
}

// ---------------- zero-init for atomic epilogue ------------------------------
__global__ void zero_out_k(float* __restrict__ out) {
    const size_t n = (size_t)MROWS * VOUT;
    const size_t i = ((size_t)blockIdx.x * blockDim.x + threadIdx.x) * 4;
    if (i + 4 <= n) {
        *reinterpret_cast<float4*>(out + i) = make_float4(0.f, 0.f, 0.f, 0.f);
    } else {
        for (size_t j = i; j < n; ++j) out[j] = 0.f;
    }
}

// dummy no-op kernels: position the GEMM at launch index 5 for ncu -s 5 -c 1
__global__ void dummy_k() {}

// ---------------- PTX helpers -----------------------------------------------
__device__ __forceinline__ void cp_async16(void* smem, const void* gmem) {
    uint32_t s = (uint32_t)__cvta_generic_to_shared(smem);
    asm volatile("cp.async.cg.shared.global [%0], [%1], 16;\n" :: "r"(s), "l"(gmem));
}
__device__ __forceinline__ void cp_commit() {
    asm volatile("cp.async.commit_group;\n" ::: "memory");
}
template<int N> __device__ __forceinline__ void cp_wait() {
    asm volatile("cp.async.wait_group %0;\n" :: "n"(N) : "memory");
}
__device__ __forceinline__ void ldsm_x4(uint32_t& r0, uint32_t& r1, uint32_t& r2,
                                        uint32_t& r3, const void* p) {
    uint32_t s = (uint32_t)__cvta_generic_to_shared(p);
    asm volatile("ldmatrix.sync.aligned.m8n8.x4.shared.b16 {%0,%1,%2,%3}, [%4];\n"
                 : "=r"(r0), "=r"(r1), "=r"(r2), "=r"(r3) : "r"(s));
}
__device__ __forceinline__ void mma16816(float* c, const uint32_t* a, const uint32_t* b) {
    asm volatile("mma.sync.aligned.m16n8k16.row.col.f32.f16.f16.f32 "
                 "{%0,%1,%2,%3}, {%4,%5,%6,%7}, {%8,%9}, {%0,%1,%2,%3};\n"
                 : "+f"(c[0]), "+f"(c[1]), "+f"(c[2]), "+f"(c[3])
                 : "r"(a[0]), "r"(a[1]), "r"(a[2]), "r"(a[3]),
                   "r"(b[0]), "r"(b[1]));
}

// ---------------- split-K GEMM with atomic epilogue --------------------------
// CTA tile 128x128, 4 warps (2x2), warp tile 64x64, 128 thr, 2 CTAs/SM.
#define BM 128
#define BN 128
#define KC 64
#define STAGES 3
#define NSTG_S (KSPLIT / KC)    // 54
#define LDS_K 72                // 64 + 8 pad halves: LDSM conflict-free
#define A_HALVES (BM * LDS_K)   // 9216
#define B_HALVES (BN * LDS_K)   // 9216
#define STG_HALVES (A_HALVES + B_HALVES)       // 18432
#define SMEM_BYTES (STAGES * STG_HALVES * 2)   // 110,592 B per CTA

__global__ __launch_bounds__(128, 2) void gemm_kernel(float* __restrict__ out) {
    extern __shared__ __align__(16) __half sm[];

    const int tid  = threadIdx.x;
    const int lane = tid & 31;
    const int warp = tid >> 5;    // 0..3
    const int wm   = warp & 1;    // m offset wm*64
    const int wn   = warp >> 1;   // n offset wn*64
    const int bn    = blockIdx.x * BN;
    const int split = blockIdx.y;
    const int bm    = blockIdx.z * BM;

    const __half* Ag = g_Xh + (size_t)bm * KPAD + (size_t)split * KSPLIT;
    const __half* Bg = g_Mh + (size_t)bn * KPAD + (size_t)split * KSPLIT;

    auto loadStage = [&](int s) {
        __half* aS = sm + (s % STAGES) * STG_HALVES;
        __half* bS = aS + A_HALVES;
        const int kb = s * KC;
        #pragma unroll
        for (int i = 0; i < 8; ++i) {
            const int c = tid + i * 128;
            const int r = c >> 3, k16 = c & 7;
            cp_async16(aS + r * LDS_K + k16 * 8,
                       Ag + (size_t)r * KPAD + kb + k16 * 8);
        }
        #pragma unroll
        for (int i = 0; i < 8; ++i) {
            const int c = tid + i * 128;
            const int r = c >> 3, k16 = c & 7;
            cp_async16(bS + r * LDS_K + k16 * 8,
                       Bg + (size_t)r * KPAD + kb + k16 * 8);
        }
    };

    float acc[4][8][4];
    #pragma unroll
    for (int i = 0; i < 4; ++i)
        #pragma unroll
        for (int j = 0; j < 8; ++j)
            #pragma unroll
            for (int e = 0; e < 4; ++e) acc[i][j][e] = 0.0f;

    loadStage(0); cp_commit();
    loadStage(1); cp_commit();
    cp_wait<1>();
    __syncthreads();               // stage 0 resident

    for (int kt = 0; kt < NSTG_S; ++kt) {
        if (kt + 2 < NSTG_S) loadStage(kt + 2);
        cp_commit();

        const __half* aS = sm + (kt % STAGES) * STG_HALVES;
        const __half* bS = aS + A_HALVES;

        #pragma unroll
        for (int ks = 0; ks < 4; ++ks) {
            const int kstep = ks * 16;
            uint32_t a[4][4];
            uint32_t b[8][2];
            #pragma unroll
            for (int i = 0; i < 4; ++i) {
                const int row = wm * 64 + i * 16 + (lane & 15);
                const int col = kstep + (lane >> 4) * 8;
                ldsm_x4(a[i][0], a[i][1], a[i][2], a[i][3], aS + row * LDS_K + col);
            }
            #pragma unroll
            for (int j = 0; j < 4; ++j) {
                const int nrow = wn * 64 + j * 16 + (lane & 7) + ((lane >> 4) << 3);
                const int col  = kstep + (((lane >> 3) & 1) << 3);
                uint32_t t0, t1, t2, t3;
                ldsm_x4(t0, t1, t2, t3, bS + nrow * LDS_K + col);
                b[2 * j][0] = t0;     b[2 * j][1] = t1;
                b[2 * j + 1][0] = t2; b[2 * j + 1][1] = t3;
            }
            #pragma unroll
            for (int i = 0; i < 4; ++i)
                #pragma unroll
                for (int jn = 0; jn < 8; ++jn)
                    mma16816(acc[i][jn], a[i], b[jn]);
        }

        cp_wait<1>();
        __syncthreads();
    }

    // epilogue: RED.add fp32 into out (zero-initialized). Two-way fp32 add is
    // commutative -> bit-deterministic across the 2 splits.
    const int g  = lane >> 2;
    const int tc = lane & 3;
    #pragma unroll
    for (int i = 0; i < 4; ++i) {
        #pragma unroll
        for (int jn = 0; jn < 8; ++jn) {
            const int row = bm + wm * 64 + i * 16 + g;
            const int col = bn + wn * 64 + jn * 8 + tc * 2;
            if (col < VOUT) {
                atomicAdd(&out[(size_t)row * VOUT + col],       acc[i][jn][0]);
                atomicAdd(&out[(size_t)(row + 8) * VOUT + col], acc[i][jn][2]);
            }
            if (col + 1 < VOUT) {
                atomicAdd(&out[(size_t)row * VOUT + col + 1],       acc[i][jn][1]);
                atomicAdd(&out[(size_t)(row + 8) * VOUT + col + 1], acc[i][jn][3]);
            }
        }
    }
}

// ---------------- entry ------------------------------------------------------
extern "C" void kernel_launch(void* const* d_in, const int* in_sizes, int n_in,
                              void* d_out, int out_size) {
    const float* x = (const float*)d_in[0];  // (32,256,6890) fp32
    const float* M = (const float*)d_in[1];  // (1723,6890) fp32
    float* out = (float*)d_out;              // (32,256,1723) fp32

    cudaFuncSetAttribute(gemm_kernel, cudaFuncAttributeMaxDynamicSharedMemorySize,
                         SMEM_BYTES);

    const size_t n_out = (size_t)MROWS * VOUT;
    // launch indices:      0          1          2         3        4      5
    // (ncu -s 5 -c 1 captures the GEMM)
    convert_x_v<<<dim3((KPAD / 8 + 127) / 128, MROWS), 128>>>(x);        // 0
    convert_m_v<<<dim3((KPAD / 8 + 127) / 128, NPAD),  128>>>(M);        // 1
    zero_out_k<<<(unsigned)((n_out / 4 + 255) / 256), 256>>>(out);       // 2
    dummy_k<<<1, 32>>>();                                                // 3
    dummy_k<<<1, 32>>>();                                                // 4
    gemm_kernel<<<dim3(NPAD / BN, NSPLIT, MROWS / BM), 128, SMEM_BYTES>>>(out); // 5
}

// round 10
// speedup vs baseline: 1.5513x; 1.5513x over previous
#include <cuda_runtime.h>
#include <cuda_fp16.h>
#include <cstdint>

// ---------------- problem constants -----------------------------------------
#define MROWS 8192      // B*C = 32*256
#define VIN   6890
#define VOUT  1723
#define KPAD  6912      // 108 * 64
#define NPAD  1792      // 14 * 128
#define NSPLIT 2
#define KSPLIT (KPAD / NSPLIT)   // 3456

// fp16 scratch + fp32 split-K partials (device globals; no runtime allocation)
__device__ __align__(16) __half g_Xh[(size_t)MROWS * KPAD];            // ~113 MB
__device__ __align__(16) __half g_Mh[(size_t)NPAD  * KPAD];            // ~25 MB
__device__ __align__(16) float  g_P[(size_t)NSPLIT * MROWS * NPAD];    // ~117 MB

// ---------------- vectorized fp32 -> fp16 conversion ------------------------
__global__ void convert_x_v(const float* __restrict__ x) {
    int k8 = blockIdx.x * blockDim.x + threadIdx.x;
    if (k8 >= KPAD / 8) return;
    int row = blockIdx.y;
    int k = k8 * 8;
    const float* src = x + (size_t)row * VIN + k;
    __align__(16) __half h[8];
    if (k + 8 <= VIN) {
        #pragma unroll
        for (int j = 0; j < 4; ++j) {
            float2 f = *reinterpret_cast<const float2*>(src + 2 * j);
            h[2 * j]     = __float2half(f.x);
            h[2 * j + 1] = __float2half(f.y);
        }
    } else {
        #pragma unroll
        for (int j = 0; j < 8; ++j)
            h[j] = (k + j < VIN) ? __float2half(src[j]) : __float2half(0.0f);
    }
    *reinterpret_cast<uint4*>(&g_Xh[(size_t)row * KPAD + k]) =
        *reinterpret_cast<const uint4*>(h);
}

__global__ void convert_m_v(const float* __restrict__ m) {
    int k8 = blockIdx.x * blockDim.x + threadIdx.x;
    if (k8 >= KPAD / 8) return;
    int row = blockIdx.y;
    int k = k8 * 8;
    __align__(16) __half h[8];
    if (row < VOUT) {
        const float* src = m + (size_t)row * VIN + k;
        if (k + 8 <= VIN) {
            #pragma unroll
            for (int j = 0; j < 4; ++j) {
                float2 f = *reinterpret_cast<const float2*>(src + 2 * j);
                h[2 * j]     = __float2half(f.x);
                h[2 * j + 1] = __float2half(f.y);
            }
        } else {
            #pragma unroll
            for (int j = 0; j < 8; ++j)
                h[j] = (k + j < VIN) ? __float2half(src[j]) : __float2half(0.0f);
        }
    } else {
        #pragma unroll
        for (int j = 0; j < 8; ++j) h[j] = __float2half(0.0f);
    }
    *reinterpret_cast<uint4*>(&g_Mh[(size_t)row * KPAD + k]) =
        *reinterpret_cast<const uint4*>(h);
}

// ---------------- PTX helpers -----------------------------------------------
__device__ __forceinline__ void cp_async16(void* smem, const void* gmem) {
    uint32_t s = (uint32_t)__cvta_generic_to_shared(smem);
    asm volatile("cp.async.cg.shared.global [%0], [%1], 16;\n" :: "r"(s), "l"(gmem));
}
__device__ __forceinline__ void cp_commit() {
    asm volatile("cp.async.commit_group;\n" ::: "memory");
}
template<int N> __device__ __forceinline__ void cp_wait() {
    asm volatile("cp.async.wait_group %0;\n" :: "n"(N) : "memory");
}
__device__ __forceinline__ void ldsm_x4(uint32_t& r0, uint32_t& r1, uint32_t& r2,
                                        uint32_t& r3, const void* p) {
    uint32_t s = (uint32_t)__cvta_generic_to_shared(p);
    asm volatile("ldmatrix.sync.aligned.m8n8.x4.shared.b16 {%0,%1,%2,%3}, [%4];\n"
                 : "=r"(r0), "=r"(r1), "=r"(r2), "=r"(r3) : "r"(s));
}
__device__ __forceinline__ void mma16816(float* c, const uint32_t* a, const uint32_t* b) {
    asm volatile("mma.sync.aligned.m16n8k16.row.col.f32.f16.f16.f32 "
                 "{%0,%1,%2,%3}, {%4,%5,%6,%7}, {%8,%9}, {%0,%1,%2,%3};\n"
                 : "+f"(c[0]), "+f"(c[1]), "+f"(c[2]), "+f"(c[3])
                 : "r"(a[0]), "r"(a[1]), "r"(a[2]), "r"(a[3]),
                   "r"(b[0]), "r"(b[1]));
}

// ---------------- split-K GEMM ------------------------------------------------
// CTA tile 128x128, 8 warps (2x4), warp tile 64x32 (best measured core:
// 16 warps/SM at occ 2 -> 84% of crossbar floor). Split-K2 cuts the wave
// quantization from 1.32 to 1.157.
#define BM 128
#define BN 128
#define KC 64
#define STAGES 3
#define NSTG_S (KSPLIT / KC)    // 54
#define LDS_K 72                // 64 + 8 pad halves: LDSM conflict-free
#define A_HALVES (BM * LDS_K)   // 9216
#define B_HALVES (BN * LDS_K)   // 9216
#define STG_HALVES (A_HALVES + B_HALVES)       // 18432
#define SMEM_BYTES (STAGES * STG_HALVES * 2)   // 110,592 B per CTA

__global__ __launch_bounds__(256, 2) void gemm_kernel() {
    extern __shared__ __align__(16) __half sm[];

    const int tid  = threadIdx.x;
    const int lane = tid & 31;
    const int warp = tid >> 5;
    const int wm   = warp & 1;    // m offset wm*64
    const int wn   = warp >> 1;   // n offset wn*32
    const int bn    = blockIdx.x * BN;
    const int split = blockIdx.y;
    const int bm    = blockIdx.z * BM;

    const __half* Ag = g_Xh + (size_t)bm * KPAD + (size_t)split * KSPLIT;
    const __half* Bg = g_Mh + (size_t)bn * KPAD + (size_t)split * KSPLIT;

    auto loadStage = [&](int s) {
        __half* aS = sm + (s % STAGES) * STG_HALVES;
        __half* bS = aS + A_HALVES;
        const int kb = s * KC;
        #pragma unroll
        for (int i = 0; i < 4; ++i) {          // A: 1024 chunks / 256 thr
            const int c = tid + i * 256;
            const int r = c >> 3, k16 = c & 7;
            cp_async16(aS + r * LDS_K + k16 * 8,
                       Ag + (size_t)r * KPAD + kb + k16 * 8);
        }
        #pragma unroll
        for (int i = 0; i < 4; ++i) {          // B: 1024 chunks / 256 thr
            const int c = tid + i * 256;
            const int r = c >> 3, k16 = c & 7;
            cp_async16(bS + r * LDS_K + k16 * 8,
                       Bg + (size_t)r * KPAD + kb + k16 * 8);
        }
    };

    float acc[4][4][4];
    #pragma unroll
    for (int i = 0; i < 4; ++i)
        #pragma unroll
        for (int j = 0; j < 4; ++j)
            #pragma unroll
            for (int e = 0; e < 4; ++e) acc[i][j][e] = 0.0f;

    loadStage(0); cp_commit();
    loadStage(1); cp_commit();
    cp_wait<1>();
    __syncthreads();               // stage 0 resident

    for (int kt = 0; kt < NSTG_S; ++kt) {
        if (kt + 2 < NSTG_S) loadStage(kt + 2);
        cp_commit();

        const __half* aS = sm + (kt % STAGES) * STG_HALVES;
        const __half* bS = aS + A_HALVES;

        #pragma unroll
        for (int ks = 0; ks < 4; ++ks) {
            const int kstep = ks * 16;
            uint32_t a[4][4];
            uint32_t b[4][2];
            #pragma unroll
            for (int i = 0; i < 4; ++i) {
                const int row = wm * 64 + i * 16 + (lane & 15);
                const int col = kstep + (lane >> 4) * 8;
                ldsm_x4(a[i][0], a[i][1], a[i][2], a[i][3], aS + row * LDS_K + col);
            }
            #pragma unroll
            for (int j = 0; j < 2; ++j) {
                const int nrow = wn * 32 + j * 16 + (lane & 7) + ((lane >> 4) << 3);
                const int col  = kstep + (((lane >> 3) & 1) << 3);
                uint32_t t0, t1, t2, t3;
                ldsm_x4(t0, t1, t2, t3, bS + nrow * LDS_K + col);
                b[2 * j][0] = t0;     b[2 * j][1] = t1;
                b[2 * j + 1][0] = t2; b[2 * j + 1][1] = t3;
            }
            #pragma unroll
            for (int i = 0; i < 4; ++i)
                #pragma unroll
                for (int jn = 0; jn < 4; ++jn)
                    mma16816(acc[i][jn], a[i], b[jn]);
        }

        cp_wait<1>();
        __syncthreads();           // stage kt+1 resident; all warps done with kt
    }

    // epilogue: unguarded float2 stores into NPAD-stride partial buffer
    float* P = g_P + (size_t)split * MROWS * NPAD;
    const int g  = lane >> 2;
    const int tc = lane & 3;
    #pragma unroll
    for (int i = 0; i < 4; ++i) {
        #pragma unroll
        for (int jn = 0; jn < 4; ++jn) {
            const int row = bm + wm * 64 + i * 16 + g;
            const int col = bn + wn * 32 + jn * 8 + tc * 2;
            *reinterpret_cast<float2*>(&P[(size_t)row * NPAD + col]) =
                make_float2(acc[i][jn][0], acc[i][jn][1]);
            *reinterpret_cast<float2*>(&P[(size_t)(row + 8) * NPAD + col]) =
                make_float2(acc[i][jn][2], acc[i][jn][3]);
        }
    }
}

// ---------------- split-K reduction: out = P0 + P1 (VOUT-packed) -------------
__global__ void reduce_k(float* __restrict__ out) {
    const size_t idx = (size_t)blockIdx.x * blockDim.x + threadIdx.x;
    const size_t ngroups = (size_t)MROWS * (NPAD / 4);
    if (idx >= ngroups) return;
    const int row = (int)(idx / (NPAD / 4));
    const int col = (int)(idx % (NPAD / 4)) * 4;
    const size_t off = (size_t)row * NPAD + col;
    float4 a = *reinterpret_cast<const float4*>(&g_P[off]);
    float4 b = *reinterpret_cast<const float4*>(&g_P[(size_t)MROWS * NPAD + off]);
    float v[4] = {a.x + b.x, a.y + b.y, a.z + b.z, a.w + b.w};
    float* orow = out + (size_t)row * VOUT;
    #pragma unroll
    for (int j = 0; j < 4; ++j)
        if (col + j < VOUT) orow[col + j] = v[j];
}

// ---------------- entry ------------------------------------------------------
extern "C" void kernel_launch(void* const* d_in, const int* in_sizes, int n_in,
                              void* d_out, int out_size) {
    const float* x = (const float*)d_in[0];  // (32,256,6890) fp32
    const float* M = (const float*)d_in[1];  // (1723,6890) fp32
    float* out = (float*)d_out;              // (32,256,1723) fp32

    cudaFuncSetAttribute(gemm_kernel, cudaFuncAttributeMaxDynamicSharedMemorySize,
                         SMEM_BYTES);

    convert_x_v<<<dim3((KPAD / 8 + 127) / 128, MROWS), 128>>>(x);
    convert_m_v<<<dim3((KPAD / 8 + 127) / 128, NPAD),  128>>>(M);
    gemm_kernel<<<dim3(NPAD / BN, NSPLIT, MROWS / BM), 256, SMEM_BYTES>>>();
    const size_t ngroups = (size_t)MROWS * (NPAD / 4);
    reduce_k<<<(unsigned)((ngroups + 255) / 256), 256>>>(out);
}

// round 11
// speedup vs baseline: 1.6219x; 1.0455x over previous
#include <cuda_runtime.h>
#include <cuda_fp16.h>
#include <cstdint>

// ---------------- problem constants -----------------------------------------
#define MROWS 8192      // B*C = 32*256
#define VIN   6890
#define VOUT  1723
#define KPAD  6912      // 108 * 64
#define NPAD  1792      // 14 * 128

// fp16 scratch (device globals; no runtime allocation)
__device__ __align__(16) __half g_Xh[(size_t)MROWS * KPAD];  // ~113 MB
__device__ __align__(16) __half g_Mh[(size_t)NPAD  * KPAD];  // ~25 MB

// ---------------- vectorized fp32 -> fp16 conversion ------------------------
__global__ void convert_x_v(const float* __restrict__ x) {
    int k8 = blockIdx.x * blockDim.x + threadIdx.x;
    if (k8 >= KPAD / 8) return;
    int row = blockIdx.y;
    int k = k8 * 8;
    const float* src = x + (size_t)row * VIN + k;
    __align__(16) __half h[8];
    if (k + 8 <= VIN) {
        #pragma unroll
        for (int j = 0; j < 4; ++j) {
            float2 f = *reinterpret_cast<const float2*>(src + 2 * j);
            h[2 * j]     = __float2half(f.x);
            h[2 * j + 1] = __float2half(f.y);
        }
    } else {
        #pragma unroll
        for (int j = 0; j < 8; ++j)
            h[j] = (k + j < VIN) ? __float2half(src[j]) : __float2half(0.0f);
    }
    *reinterpret_cast<uint4*>(&g_Xh[(size_t)row * KPAD + k]) =
        *reinterpret_cast<const uint4*>(h);
}

__global__ void convert_m_v(const float* __restrict__ m) {
    int k8 = blockIdx.x * blockDim.x + threadIdx.x;
    if (k8 >= KPAD / 8) return;
    int row = blockIdx.y;
    int k = k8 * 8;
    __align__(16) __half h[8];
    if (row < VOUT) {
        const float* src = m + (size_t)row * VIN + k;
        if (k + 8 <= VIN) {
            #pragma unroll
            for (int j = 0; j < 4; ++j) {
                float2 f = *reinterpret_cast<const float2*>(src + 2 * j);
                h[2 * j]     = __float2half(f.x);
                h[2 * j + 1] = __float2half(f.y);
            }
        } else {
            #pragma unroll
            for (int j = 0; j < 8; ++j)
                h[j] = (k + j < VIN) ? __float2half(src[j]) : __float2half(0.0f);
        }
    } else {
        #pragma unroll
        for (int j = 0; j < 8; ++j) h[j] = __float2half(0.0f);
    }
    *reinterpret_cast<uint4*>(&g_Mh[(size_t)row * KPAD + k]) =
        *reinterpret_cast<const uint4*>(h);
}

// ---------------- PTX helpers -----------------------------------------------
__device__ __forceinline__ void cp_async16(void* smem, const void* gmem) {
    uint32_t s = (uint32_t)__cvta_generic_to_shared(smem);
    asm volatile("cp.async.cg.shared.global [%0], [%1], 16;\n" :: "r"(s), "l"(gmem));
}
__device__ __forceinline__ void cp_commit() {
    asm volatile("cp.async.commit_group;\n" ::: "memory");
}
template<int N> __device__ __forceinline__ void cp_wait() {
    asm volatile("cp.async.wait_group %0;\n" :: "n"(N) : "memory");
}
__device__ __forceinline__ void ldsm_x4(uint32_t& r0, uint32_t& r1, uint32_t& r2,
                                        uint32_t& r3, const void* p) {
    uint32_t s = (uint32_t)__cvta_generic_to_shared(p);
    asm volatile("ldmatrix.sync.aligned.m8n8.x4.shared.b16 {%0,%1,%2,%3}, [%4];\n"
                 : "=r"(r0), "=r"(r1), "=r"(r2), "=r"(r3) : "r"(s));
}
__device__ __forceinline__ void mma16816(float* c, const uint32_t* a, const uint32_t* b) {
    asm volatile("mma.sync.aligned.m16n8k16.row.col.f32.f16.f16.f32 "
                 "{%0,%1,%2,%3}, {%4,%5,%6,%7}, {%8,%9}, {%0,%1,%2,%3};\n"
                 : "+f"(c[0]), "+f"(c[1]), "+f"(c[2]), "+f"(c[3])
                 : "r"(a[0]), "r"(a[1]), "r"(a[2]), "r"(a[3]),
                   "r"(b[0]), "r"(b[1]));
}

// ---------------- GEMM: C[8192,1723] = Xh * Mh^T ----------------------------
// CTA tile 128x128, 4 warps (2x2), warp tile 64x64 (lowest crossbar B/MAC),
// 128 thr/CTA, occ 2 (256 regs/thread budget -> fragment double-buffering).
#define BM 128
#define BN 128
#define KC 64
#define STAGES 3
#define NSTG (KPAD / KC)        // 108
#define LDS_K 72                // 64 + 8 pad halves: LDSM conflict-free
#define A_HALVES (BM * LDS_K)   // 9216
#define B_HALVES (BN * LDS_K)   // 9216
#define STG_HALVES (A_HALVES + B_HALVES)       // 18432
#define SMEM_BYTES (STAGES * STG_HALVES * 2)   // 110,592 B per CTA

__global__ __launch_bounds__(128, 2) void gemm_kernel(float* __restrict__ out) {
    extern __shared__ __align__(16) __half sm[];

    const int tid  = threadIdx.x;
    const int lane = tid & 31;
    const int warp = tid >> 5;    // 0..3
    const int wm   = warp & 1;    // m offset wm*64
    const int wn   = warp >> 1;   // n offset wn*64
    const int bn   = blockIdx.x * BN;
    const int bm   = blockIdx.y * BM;

    const __half* Ag = g_Xh + (size_t)bm * KPAD;
    const __half* Bg = g_Mh + (size_t)bn * KPAD;

    auto loadStage = [&](int s) {
        __half* aS = sm + (s % STAGES) * STG_HALVES;
        __half* bS = aS + A_HALVES;
        const int kb = s * KC;
        #pragma unroll
        for (int i = 0; i < 8; ++i) {          // A: 1024 chunks / 128 thr
            const int c = tid + i * 128;
            const int r = c >> 3, k16 = c & 7;
            cp_async16(aS + r * LDS_K + k16 * 8,
                       Ag + (size_t)r * KPAD + kb + k16 * 8);
        }
        #pragma unroll
        for (int i = 0; i < 8; ++i) {          // B: 1024 chunks / 128 thr
            const int c = tid + i * 128;
            const int r = c >> 3, k16 = c & 7;
            cp_async16(bS + r * LDS_K + k16 * 8,
                       Bg + (size_t)r * KPAD + kb + k16 * 8);
        }
    };

    // double-buffered fragments (ks-level software pipeline)
    uint32_t afr[2][4][4];
    uint32_t bfr[2][8][2];

    // per-warp LDSM base addresses (row parts independent of ks)
    const int a_row = wm * 64 + (lane & 15);
    const int a_colsel = (lane >> 4) * 8;
    const int b_row = wn * 64 + (lane & 7) + ((lane >> 4) << 3);
    const int b_colsel = ((lane >> 3) & 1) << 3;

    auto loadFrags = [&](const __half* aS, const __half* bS, int ks, int buf) {
        const int kstep = ks * 16;
        #pragma unroll
        for (int i = 0; i < 4; ++i)
            ldsm_x4(afr[buf][i][0], afr[buf][i][1], afr[buf][i][2], afr[buf][i][3],
                    aS + (a_row + i * 16) * LDS_K + kstep + a_colsel);
        #pragma unroll
        for (int j = 0; j < 4; ++j) {
            uint32_t t0, t1, t2, t3;
            ldsm_x4(t0, t1, t2, t3,
                    bS + (b_row + j * 16) * LDS_K + kstep + b_colsel);
            bfr[buf][2 * j][0] = t0;     bfr[buf][2 * j][1] = t1;
            bfr[buf][2 * j + 1][0] = t2; bfr[buf][2 * j + 1][1] = t3;
        }
    };

    float acc[4][8][4];
    #pragma unroll
    for (int i = 0; i < 4; ++i)
        #pragma unroll
        for (int j = 0; j < 8; ++j)
            #pragma unroll
            for (int e = 0; e < 4; ++e) acc[i][j][e] = 0.0f;

    loadStage(0); cp_commit();
    loadStage(1); cp_commit();
    cp_wait<1>();
    __syncthreads();               // stage 0 resident

    for (int kt = 0; kt < NSTG; ++kt) {
        if (kt + 2 < NSTG) loadStage(kt + 2);
        cp_commit();

        const __half* aS = sm + (kt % STAGES) * STG_HALVES;
        const __half* bS = aS + A_HALVES;

        loadFrags(aS, bS, 0, 0);   // prime ks=0
        #pragma unroll
        for (int ks = 0; ks < 4; ++ks) {
            const int cur = ks & 1;
            if (ks < 3) loadFrags(aS, bS, ks + 1, cur ^ 1);  // prefetch next
            #pragma unroll
            for (int i = 0; i < 4; ++i)
                #pragma unroll
                for (int jn = 0; jn < 8; ++jn)
                    mma16816(acc[i][jn], afr[cur][i], bfr[cur][jn]);
        }

        cp_wait<1>();
        __syncthreads();           // stage kt+1 resident; all warps done with kt
    }

    // epilogue: scalar fp32 guarded stores (VOUT=1723 odd)
    const int g  = lane >> 2;
    const int tc = lane & 3;
    #pragma unroll
    for (int i = 0; i < 4; ++i) {
        #pragma unroll
        for (int jn = 0; jn < 8; ++jn) {
            const int row = bm + wm * 64 + i * 16 + g;
            const int col = bn + wn * 64 + jn * 8 + tc * 2;
            if (col < VOUT)     out[(size_t)row * VOUT + col]           = acc[i][jn][0];
            if (col + 1 < VOUT) out[(size_t)row * VOUT + col + 1]       = acc[i][jn][1];
            if (col < VOUT)     out[(size_t)(row + 8) * VOUT + col]     = acc[i][jn][2];
            if (col + 1 < VOUT) out[(size_t)(row + 8) * VOUT + col + 1] = acc[i][jn][3];
        }
    }
}

// ---------------- entry ------------------------------------------------------
extern "C" void kernel_launch(void* const* d_in, const int* in_sizes, int n_in,
                              void* d_out, int out_size) {
    const float* x = (const float*)d_in[0];  // (32,256,6890) fp32
    const float* M = (const float*)d_in[1];  // (1723,6890) fp32
    float* out = (float*)d_out;              // (32,256,1723) fp32

    cudaFuncSetAttribute(gemm_kernel, cudaFuncAttributeMaxDynamicSharedMemorySize,
                         SMEM_BYTES);

    convert_x_v<<<dim3((KPAD / 8 + 127) / 128, MROWS), 128>>>(x);
    convert_m_v<<<dim3((KPAD / 8 + 127) / 128, NPAD),  128>>>(M);
    gemm_kernel<<<dim3(NPAD / BN, MROWS / BM), 128, SMEM_BYTES>>>(out);
}